// round 16
// baseline (speedup 1.0000x reference)
#include <cuda_runtime.h>

// 12-qubit, 4-layer variational circuit simulator — R15.
// Limiter analysis: every 256-thread variant is stuck at ~3.5 warps/SMSP
// (grid fixed at 256 CTAs) -> issue ~36%. R7/R11's 512-thread fix died on
// shfl MIO cost. R15: 512 threads x 8 amps, FOUR 3-qubit register-local
// passes, zero shfl (+33% smem traffic, +100% warps).
//  - P0/P1 share warp-private set {bits8-11=w}; P2/P3 share {bits2-5=w}
//    -> syncwarp inside pairs, 2 full barriers/layer
//  - per-pass lane->bit assignments give half-warp bank strides {2,4,8,16}
//    under slot(i)=i+(i>>4)+(i>>8): conflict-free LDS/STS everywhere
//  - fused trainable-RZ diag per pass is now 8 entries, no side handling
// Retained: f32x2 packed math, separable data diagonal, CX ladder as
// permutation fused into P0 gather, ping-pong buffers, layer-0 from the
// constant state, __launch_bounds__(512,2).

#define NT   512
#define PDIM 4368               // slot(4095)=4365 -> round up
typedef unsigned long long u64;

__device__ __forceinline__ int slot(int i) { return i + (i >> 4) + (i >> 8); }

__device__ __forceinline__ u64 pk2(float lo, float hi) {
    u64 r;
    asm("mov.b64 %0, {%1, %2};" : "=l"(r)
        : "r"(__float_as_uint(lo)), "r"(__float_as_uint(hi)));
    return r;
}
__device__ __forceinline__ void upk(u64 v, float& lo, float& hi) {
    unsigned a, b;
    asm("mov.b64 {%0, %1}, %2;" : "=r"(a), "=r"(b) : "l"(v));
    lo = __uint_as_float(a);
    hi = __uint_as_float(b);
}
__device__ __forceinline__ u64 swp(u64 v) {
    unsigned a, b;
    asm("mov.b64 {%0, %1}, %2;" : "=r"(a), "=r"(b) : "l"(v));
    u64 r;
    asm("mov.b64 %0, {%1, %2};" : "=l"(r) : "r"(b), "r"(a));
    return r;
}
__device__ __forceinline__ u64 mul2(u64 a, u64 b) {
    u64 r;
    asm("mul.rn.f32x2 %0, %1, %2;" : "=l"(r) : "l"(a), "l"(b));
    return r;
}
__device__ __forceinline__ u64 fma2(u64 a, u64 b, u64 c) {
    u64 r;
    asm("fma.rn.f32x2 %0, %1, %2, %3;" : "=l"(r) : "l"(a), "l"(b), "l"(c));
    return r;
}
// a * (pr + i*pi); phase pre-splatted r2=(pr,pr), n=(-pi,pi); a packed (re,im).
__device__ __forceinline__ u64 pmul(u64 a, u64 r2, u64 n) {
    return fma2(r2, a, mul2(n, swp(a)));
}

struct GY { u64 c2, s2, ns2; };  // (c,c) (s,s) (-s,-s)

__device__ __forceinline__ void ry2(u64& a0, u64& a1, u64 c2, u64 s2, u64 ns2) {
    u64 t0 = fma2(c2, a0, mul2(ns2, a1));
    u64 t1 = fma2(s2, a0, mul2(c2, a1));
    a0 = t0; a1 = t1;
}
// RYs on the 3 k-bits of a[8]; gates loaded per stage (bounded liveness).
__device__ __forceinline__ void ry3(u64* a, const GY* gs) {
    {
        GY g = gs[0];
        #pragma unroll
        for (int k = 0; k < 8; k += 2) ry2(a[k], a[k + 1], g.c2, g.s2, g.ns2);
    }
    {
        GY g = gs[1];
        #pragma unroll
        for (int k = 0; k < 8; k++) if (!(k & 2)) ry2(a[k], a[k | 2], g.c2, g.s2, g.ns2);
    }
    {
        GY g = gs[2];
        #pragma unroll
        for (int k = 0; k < 4; k++) ry2(a[k], a[k | 4], g.c2, g.s2, g.ns2);
    }
}
// Fused trainable-RZ diagonal for one pass (8 entries indexed by k).
__device__ __forceinline__ void diag8(u64* a, const ulonglong2* dP) {
    #pragma unroll
    for (int k = 0; k < 8; k++) { ulonglong2 d = dP[k]; a[k] = pmul(a[k], d.x, d.y); }
}

__global__ void __launch_bounds__(NT, 2)
qsim_kernel(const float* __restrict__ x, const float* __restrict__ w,
            float* __restrict__ out) {
    extern __shared__ u64 amp[];        // [2][PDIM] ping-pong, padded layout
    __shared__ GY gy[48];               // RY splats
    __shared__ ulonglong2 gd[16 * 8];   // fused-RZ diag splats per (layer,pass)
    __shared__ ulonglong2 tlP[64];      // data-diag qubits 0..5 splats, permuted
    __shared__ ulonglong2 th[64];       // data-diag qubits 6..11 splats
    __shared__ float red[16];

    const int tid = threadIdx.x;

    // ---- precompute (one sincos per thread-slot) ----
    if (tid < 48) {                               // RY gate splats
        float c, s;
        sincosf(0.5f * w[2 * tid], &s, &c);
        gy[tid].c2 = pk2(c, c);
        gy[tid].s2 = pk2(s, s);
        gy[tid].ns2 = pk2(-s, -s);
    }
    if (tid >= 64 && tid < 192) {                 // fused trainable-RZ diagonals
        int idx = tid - 64;                       // pass p = idx>>3 (layer*4+sub), m = idx&7
        int p = idx >> 3, m = idx & 7;
        int layer = p >> 2, sub = p & 3;
        const float* wz = w + 2 * (layer * 12 + sub * 3);
        float t = 0.f;
        #pragma unroll
        for (int j = 0; j < 3; j++)
            t += (((m >> j) & 1) ? 0.5f : -0.5f) * wz[2 * j + 1];
        float di, dr;
        sincosf(t, &di, &dr);
        gd[idx] = make_ulonglong2(pk2(dr, dr), pk2(-di, di));
    }
    if (tid >= 256 && tid < 384) {                // separable data-diagonal tables
        const float* xv = x + blockIdx.x * 12;
        int m = (tid - 256) & 63;
        const float* xs = xv + ((tid < 320) ? 6 : 0);   // 256..319 -> th, 320..383 -> tlP
        float a = 0.f;
        #pragma unroll
        for (int q = 0; q < 6; q++) a += ((m >> q) & 1) ? xs[q] : -xs[q];
        a *= 0.5f;
        float sn, cs;
        sincosf(a, &sn, &cs);
        ulonglong2 e = make_ulonglong2(pk2(cs, cs), pk2(-sn, sn));
        if (tid < 320) th[m] = e;
        else           tlP[((m & 7) << 3) | (m >> 3)] = e;   // [k][low3] layout
    }
    __syncthreads();

    // pass mappings (i = state index, W = tid>>5, L = tid&31, k = 0..7):
    //  P0: i = 256W + 8L + k               (q0-2)  slot = 273W + 8L + (L>>1) + k
    //  P1: i = (L>>2) + 8k + 64(L&3) + 256W (q3-5) slot = base1 + 8k + (k>>1)
    //  P2: i = (L&3) + 4W + 64k + 512*L4 + 1024*((L>>2)&3)   (q6-8)
    //      slot = base2 + 68k + (k>>2)
    //  P3: i = L4 | (L1<<1) | (W<<2) | (L2<<6) | (L3<<7) | (L0<<8) | (k<<9) (q9-11)
    //      slot = base3 + 546k
    //  P0/P1 share {bits8-11=W}; P2/P3 share {bits2-5=W} -> syncwarp inside pairs.
    const int W = tid >> 5, L = tid & 31;
    const int iB0 = 256 * W + 8 * L;
    const int sB0 = 273 * W + 8 * L + (L >> 1);
    const int sB1 = (L >> 2) + 68 * (L & 3) + 273 * W;
    const int sB2 = (L & 3) + 4 * W + (W >> 2)
                  + 546 * ((L >> 4) & 1) + 1092 * ((L >> 2) & 3);
    const int sB3 = ((L >> 4) & 1) + 2 * ((L >> 1) & 1) + 4 * W + (W >> 2)
                  + 68 * ((L >> 2) & 1) + 136 * ((L >> 3) & 1) + 273 * (L & 1);
    const ulonglong2 hsp = th[4 * W + (L >> 3)];  // (i>>6) data phase, thread-constant in P0
    const int tlx = L & 7;                        // tlP index = 8k + tlx

    u64* const buf0 = amp;
    u64* const buf1 = amp + PDIM;
    u64 a[8];

    #pragma unroll
    for (int l = 0; l < 4; l++) {
        u64* const cur = (l & 1) ? buf1 : buf0;
        const GY* g = gy + l * 12;
        const ulonglong2* gdl = gd + l * 32;

        // ---- P0: qubits 0-2 (+ full data diagonal; CX perm fused for l>0) ----
        if (l == 0) {
            const u64 C = pk2(0.015625f, 0.f);
            #pragma unroll
            for (int k = 0; k < 8; k++) {
                ulonglong2 t = tlP[(k << 3) | tlx];
                a[k] = pmul(pmul(C, t.x, t.y), hsp.x, hsp.y);
            }
        } else {
            u64* const prv = (l & 1) ? buf0 : buf1;
            #pragma unroll
            for (int k = 0; k < 8; k++) {
                int i = iB0 + k;
                int j = i ^ ((i << 1) & 0xFFE);   // composed CX ladder
                a[k] = prv[slot(j)];
            }
            #pragma unroll
            for (int k = 0; k < 8; k++) {
                ulonglong2 t = tlP[(k << 3) | tlx];
                a[k] = pmul(pmul(a[k], t.x, t.y), hsp.x, hsp.y);
            }
        }
        ry3(a, g);
        diag8(a, gdl);
        #pragma unroll
        for (int k = 0; k < 8; k++) cur[sB0 + k] = a[k];
        __syncwarp();

        // ---- P1: qubits 3-5 (same warp set as P0) ----
        #pragma unroll
        for (int k = 0; k < 8; k++) a[k] = cur[sB1 + 8 * k + (k >> 1)];
        ry3(a, g + 3);
        diag8(a, gdl + 8);
        #pragma unroll
        for (int k = 0; k < 8; k++) cur[sB1 + 8 * k + (k >> 1)] = a[k];
        __syncthreads();

        // ---- P2: qubits 6-8 ----
        #pragma unroll
        for (int k = 0; k < 8; k++) a[k] = cur[sB2 + 68 * k + (k >> 2)];
        ry3(a, g + 6);
        diag8(a, gdl + 16);
        #pragma unroll
        for (int k = 0; k < 8; k++) cur[sB2 + 68 * k + (k >> 2)] = a[k];
        __syncwarp();

        // ---- P3: qubits 9-11 (same warp set as P2) ----
        #pragma unroll
        for (int k = 0; k < 8; k++) a[k] = cur[sB3 + 546 * k];
        ry3(a, g + 9);
        diag8(a, gdl + 24);
        #pragma unroll
        for (int k = 0; k < 8; k++) cur[sB3 + 546 * k] = a[k];
        __syncthreads();
    }

    // ---- measurement: <Z(0)>, final CX-perm fused into the load (state in buf1) ----
    float acc = 0.f;
    #pragma unroll
    for (int k = 0; k < 8; k++) {
        int i = iB0 + k;
        int j = i ^ ((i << 1) & 0xFFE);
        float re, im;
        upk(buf1[slot(j)], re, im);
        float p = re * re + im * im;
        acc += (k & 1) ? -p : p;
    }
    #pragma unroll
    for (int off = 16; off > 0; off >>= 1)
        acc += __shfl_down_sync(0xffffffffu, acc, off);
    if ((tid & 31) == 0) red[tid >> 5] = acc;
    __syncthreads();
    if (tid == 0) {
        float t = 0.f;
        #pragma unroll
        for (int i = 0; i < 16; i++) t += red[i];
        out[blockIdx.x] = t;
    }
}

extern "C" void kernel_launch(void* const* d_in, const int* in_sizes, int n_in,
                              void* d_out, int out_size) {
    const float* x = (const float*)d_in[0];   // (256, 12) float32
    const float* w = (const float*)d_in[1];   // (96,)     float32
    float* out = (float*)d_out;               // (256, 1)  float32
    (void)in_sizes; (void)n_in; (void)out_size;
    cudaFuncSetAttribute(qsim_kernel, cudaFuncAttributeMaxDynamicSharedMemorySize,
                         2 * PDIM * (int)sizeof(u64));
    qsim_kernel<<<256, NT, 2 * PDIM * sizeof(u64)>>>(x, w, out);
}

// round 17
// speedup vs baseline: 1.3072x; 1.3072x over previous
#include <cuda_runtime.h>

// 12-qubit, 4-layer variational circuit simulator — R16.
// Base: R13 (16 amps x 256 thr, 3 round trips/layer, 21.9us). R16 removes
// instructions by exact circuit algebra:
//  - trainable-RZ diagonal of layer l is pushed through the CX ladder:
//    D_x·P·D_l = P·D~  with D~(i) = D_l(P(i))·D_x(i), still separable
//    (lo: 6-bit, hi: 7-bit since P(i)_q = i_q^i_{q-1}). It merges into the
//    pass-A diagonal tables -> per-pass diag16 deleted (all 3 passes).
//  - layer-3 trainable RZ dropped (diagonal before |.|^2 measurement).
//  - final CX perm dropped (P preserves bit0 and magnitudes) -> measurement
//    done directly in pass-C registers; last store+gather deleted.
// Retained: f32x2 packed math, padded layout slot(i)=i+(i>>4)+(i>>8)
// (conflict-free strides 1/17/273), warp-private B/C pair (syncwarp between),
// ping-pong buffers for the perm gather, __launch_bounds__(256,2).

#define NT   256
#define PDIM 4368               // slot(4095)=4365 -> round up
typedef unsigned long long u64;

__device__ __forceinline__ int slot(int i) { return i + (i >> 4) + (i >> 8); }

__device__ __forceinline__ u64 pk2(float lo, float hi) {
    u64 r;
    asm("mov.b64 %0, {%1, %2};" : "=l"(r)
        : "r"(__float_as_uint(lo)), "r"(__float_as_uint(hi)));
    return r;
}
__device__ __forceinline__ void upk(u64 v, float& lo, float& hi) {
    unsigned a, b;
    asm("mov.b64 {%0, %1}, %2;" : "=r"(a), "=r"(b) : "l"(v));
    lo = __uint_as_float(a);
    hi = __uint_as_float(b);
}
__device__ __forceinline__ u64 swp(u64 v) {
    unsigned a, b;
    asm("mov.b64 {%0, %1}, %2;" : "=r"(a), "=r"(b) : "l"(v));
    u64 r;
    asm("mov.b64 %0, {%1, %2};" : "=l"(r) : "r"(b), "r"(a));
    return r;
}
__device__ __forceinline__ u64 mul2(u64 a, u64 b) {
    u64 r;
    asm("mul.rn.f32x2 %0, %1, %2;" : "=l"(r) : "l"(a), "l"(b));
    return r;
}
__device__ __forceinline__ u64 fma2(u64 a, u64 b, u64 c) {
    u64 r;
    asm("fma.rn.f32x2 %0, %1, %2, %3;" : "=l"(r) : "l"(a), "l"(b), "l"(c));
    return r;
}
// a * (pr + i*pi); phase pre-splatted r2=(pr,pr), n=(-pi,pi); a packed (re,im).
__device__ __forceinline__ u64 pmul(u64 a, u64 r2, u64 n) {
    return fma2(r2, a, mul2(n, swp(a)));
}

struct GY { u64 c2, s2, ns2; };  // (c,c) (s,s) (-s,-s)

__device__ __forceinline__ void ry2(u64& a0, u64& a1, u64 c2, u64 s2, u64 ns2) {
    u64 t0 = fma2(c2, a0, mul2(ns2, a1));
    u64 t1 = fma2(s2, a0, mul2(c2, a1));
    a0 = t0; a1 = t1;
}
// RYs on the 4 k-bits of a[16]; gates loaded per stage (bounded liveness).
__device__ __forceinline__ void ry4(u64* a, const GY* gs) {
    {
        GY g = gs[0];
        #pragma unroll
        for (int k = 0; k < 16; k += 2) ry2(a[k], a[k + 1], g.c2, g.s2, g.ns2);
    }
    {
        GY g = gs[1];
        #pragma unroll
        for (int k = 0; k < 16; k++) if (!(k & 2)) ry2(a[k], a[k | 2], g.c2, g.s2, g.ns2);
    }
    {
        GY g = gs[2];
        #pragma unroll
        for (int k = 0; k < 16; k++) if (!(k & 4)) ry2(a[k], a[k | 4], g.c2, g.s2, g.ns2);
    }
    {
        GY g = gs[3];
        #pragma unroll
        for (int k = 0; k < 8; k++) ry2(a[k], a[k | 8], g.c2, g.s2, g.ns2);
    }
}

__global__ void __launch_bounds__(NT, 2)
qsim_kernel(const float* __restrict__ x, const float* __restrict__ w,
            float* __restrict__ out) {
    extern __shared__ u64 amp[];          // [2][PDIM] ping-pong, padded layout
    __shared__ GY gy[48];                 // RY splats
    __shared__ ulonglong2 tlo[4 * 64];    // combined diag, low 6 bits (permuted idx)
    __shared__ ulonglong2 thi[4 * 128];   // combined diag, bits 5..11 (7-bit idx)
    __shared__ float red[8];

    const int tid = threadIdx.x;
    const float* xv = x + blockIdx.x * 12;

    // ---- RY gate splats ----
    if (tid < 48) {
        float c, s;
        sincosf(0.5f * w[2 * tid], &s, &c);
        gy[tid].c2 = pk2(c, c);
        gy[tid].s2 = pk2(s, s);
        gy[tid].ns2 = pk2(-s, -s);
    }
    // ---- combined diagonal tables: slot s applied in pass A of layer s.
    //      s=0: pure data diag. s>=1: data diag * (trainable RZ of layer s-1
    //      evaluated at P(i)), where P(i)_q = i_q ^ i_{q-1}.
    //      768 entries total = 3 per thread, one sincos each. ----
    #pragma unroll
    for (int r = 0; r < 3; r++) {
        int e = tid + (r << 8);
        float ang = 0.f;
        if (e < 256) {                       // lo tables: 6-bit index m = i & 63
            int s = e >> 6, m = e & 63;
            #pragma unroll
            for (int q = 0; q < 6; q++)
                ang += ((m >> q) & 1) ? xv[q] : -xv[q];
            if (s) {
                const float* wz = w + 2 * (s - 1) * 12 + 1;  // rz(s-1, q) at wz[2q]
                int pb = m ^ (m << 1);       // bit q = m_q ^ m_{q-1} (pb_0 = m_0)
                #pragma unroll
                for (int q = 0; q < 6; q++)
                    ang += ((pb >> q) & 1) ? wz[2 * q] : -wz[2 * q];
            }
            float sn, cs;
            sincosf(0.5f * ang, &sn, &cs);
            tlo[(s << 6) | ((m & 15) << 2) | (m >> 4)] =
                make_ulonglong2(pk2(cs, cs), pk2(-sn, sn));
        } else {                             // hi tables: 7-bit index n = (i>>5)&127
            int idx = e - 256;
            int s = idx >> 7, n = idx & 127; // n_j = i_{5+j}
            #pragma unroll
            for (int q = 6; q < 12; q++)
                ang += ((n >> (q - 5)) & 1) ? xv[q] : -xv[q];
            if (s) {
                const float* wz = w + 2 * (s - 1) * 12 + 1;
                int pb = n ^ (n << 1);       // bit j = n_j ^ n_{j-1}
                #pragma unroll
                for (int q = 6; q < 12; q++)
                    ang += ((pb >> (q - 5)) & 1) ? wz[2 * q] : -wz[2 * q];
            }
            float sn, cs;
            sincosf(0.5f * ang, &sn, &cs);
            thi[(s << 7) | n] = make_ulonglong2(pk2(cs, cs), pk2(-sn, sn));
        }
    }
    __syncthreads();

    // pass mappings (i = state index, t = tid, k = 0..15, slot = i+(i>>4)+(i>>8)):
    //  A: i = (t<<4)|k            -> slot = 17t + (t>>4) + k
    //  B: i = c | (k<<4) | (h<<8) -> slot = c + 273h + 17k
    //  C: i = c | (h<<4) | (k<<8) -> slot = c + 17h  + 273k
    //  c = 2*(t>>5) + ((t>>4)&1), h = t&15; warp owns {bits0-3 in {2w,2w+1}}
    //  in BOTH B and C -> syncwarp between them.
    //  Pass-A diag indices: lo = (i&63) -> tlo[(k<<2)|(t&3)] (permuted store);
    //  hi = (i>>5)&127 = t>>1 (thread-constant).
    const int c16 = 2 * (tid >> 5) + ((tid >> 4) & 1);
    const int h16 = tid & 15;
    const int sA  = 17 * tid + (tid >> 4);
    const int sB  = c16 + 273 * h16;
    const int sC  = c16 + 17 * h16;
    const int tlx = (tid & 3);

    u64* const buf0 = amp;
    u64* const buf1 = amp + PDIM;
    u64 a[16];

    // ---- layer 0, pass A: const state * data diag (slot 0), RY q0..3 ----
    {
        const ulonglong2 hsp = thi[tid >> 1];
        const u64 C = pk2(0.015625f, 0.f);
        #pragma unroll
        for (int k = 0; k < 16; k++) {
            ulonglong2 t = tlo[(k << 2) | tlx];
            a[k] = pmul(pmul(C, t.x, t.y), hsp.x, hsp.y);
        }
        ry4(a, gy);
        #pragma unroll
        for (int k = 0; k < 16; k++) buf0[sA + k] = a[k];
        __syncthreads();
    }

    float acc = 0.f;

    #pragma unroll
    for (int l = 0; l < 4; l++) {
        u64* const cur = (l & 1) ? buf1 : buf0;
        const GY* g = gy + l * 12;

        // ---- pass B: qubits 4..7, in place on warp-private set ----
        #pragma unroll
        for (int k = 0; k < 16; k++) a[k] = cur[sB + 17 * k];
        ry4(a, g + 4);
        #pragma unroll
        for (int k = 0; k < 16; k++) cur[sB + 17 * k] = a[k];
        __syncwarp();

        // ---- pass C: qubits 8..11, in place on the SAME warp-private set ----
        #pragma unroll
        for (int k = 0; k < 16; k++) a[k] = cur[sC + 273 * k];
        ry4(a, g + 8);

        if (l < 3) {
            #pragma unroll
            for (int k = 0; k < 16; k++) cur[sC + 273 * k] = a[k];
            __syncthreads();

            // ---- pass A of layer l+1: CX-perm gather from cur, combined diag
            //      (data * trainable-RZ(l) pushed through P), RY q0..3 ----
            u64* const nxt = (l & 1) ? buf0 : buf1;
            #pragma unroll
            for (int k = 0; k < 16; k++) {
                int i = (tid << 4) | k;
                int j = i ^ ((i << 1) & 0xFFE);   // composed CX ladder
                a[k] = cur[slot(j)];
            }
            const ulonglong2* tloS = tlo + ((l + 1) << 6);
            const ulonglong2 hsp = thi[((l + 1) << 7) | (tid >> 1)];
            #pragma unroll
            for (int k = 0; k < 16; k++) {
                ulonglong2 t = tloS[(k << 2) | tlx];
                a[k] = pmul(pmul(a[k], t.x, t.y), hsp.x, hsp.y);
            }
            ry4(a, gy + (l + 1) * 12);
            #pragma unroll
            for (int k = 0; k < 16; k++) nxt[sA + k] = a[k];
            __syncthreads();
        } else {
            // ---- measurement in registers: layer-3 trainable RZ and the final
            //      CX perm are magnitude-preserving on bit0 -> skip both.
            //      bit0(i) = c16 & 1 = (tid>>4)&1, thread-constant. ----
            #pragma unroll
            for (int k = 0; k < 16; k++) {
                float re, im;
                upk(a[k], re, im);
                acc = fmaf(re, re, fmaf(im, im, acc));
            }
            if ((tid >> 4) & 1) acc = -acc;
        }
    }

    // ---- block reduction ----
    #pragma unroll
    for (int off = 16; off > 0; off >>= 1)
        acc += __shfl_down_sync(0xffffffffu, acc, off);
    if ((tid & 31) == 0) red[tid >> 5] = acc;
    __syncthreads();
    if (tid == 0) {
        float t = 0.f;
        #pragma unroll
        for (int i = 0; i < 8; i++) t += red[i];
        out[blockIdx.x] = t;
    }
}

extern "C" void kernel_launch(void* const* d_in, const int* in_sizes, int n_in,
                              void* d_out, int out_size) {
    const float* x = (const float*)d_in[0];   // (256, 12) float32
    const float* w = (const float*)d_in[1];   // (96,)     float32
    float* out = (float*)d_out;               // (256, 1)  float32
    (void)in_sizes; (void)n_in; (void)out_size;
    cudaFuncSetAttribute(qsim_kernel, cudaFuncAttributeMaxDynamicSharedMemorySize,
                         2 * PDIM * (int)sizeof(u64));
    qsim_kernel<<<256, NT, 2 * PDIM * sizeof(u64)>>>(x, w, out);
}